// round 15
// baseline (speedup 1.0000x reference)
#include <cuda_runtime.h>

#define NV 1022            // interior size
#define GV 1024            // full grid
#define SP 1024            // padded scratch row stride

#define T    4             // fused sweeps per kernel
#define OUTR 24            // valid output rows per tile
#define OUTC 56            // valid output cols per tile
#define NTR  43            // ceil(1022/24)
#define NTC  19            // ceil(1022/56)
#define NTILES (8 * NTR * NTC)

#define UH 34              // smem u rows
#define UW 72              // smem u row stride
#define KW 68              // smem kappa/f row stride
#define USZ (UH * UW)      // 2448
#define KSZ (UH * KW)      // 2312

#define HH2 (2.0f / (1023.0f * 1023.0f))   // 2*H^2

__device__ __align__(256) float g_bufA[8 * NV * SP];
__device__ __align__(256) float g_bufB[8 * NV * SP];

// ---------------------------------------------------------------------------
__device__ __forceinline__ unsigned s2u(const void* p) {
    unsigned r;
    asm("{ .reg .u64 t; cvta.to.shared.u64 t, %1; cvt.u32.u64 %0, t; }"
        : "=r"(r) : "l"(p));
    return r;
}
__device__ __forceinline__ void cp16(float* dst, const float* src, bool inb) {
    int sz = inb ? 16 : 0;
    asm volatile("cp.async.ca.shared.global [%0], [%1], 16, %2;"
                 :: "r"(s2u(dst)), "l"(src), "r"(sz) : "memory");
}
__device__ __forceinline__ void cp4(float* dst, const float* src, bool inb) {
    int sz = inb ? 4 : 0;
    asm volatile("cp.async.ca.shared.global [%0], [%1], 4, %2;"
                 :: "r"(s2u(dst)), "l"(src), "r"(sz) : "memory");
}
#define CP_COMMIT() asm volatile("cp.async.commit_group;" ::: "memory")
#define CP_WAIT0()  asm volatile("cp.async.wait_group 0;"  ::: "memory")

// Bulk GMEM->SMEM copy completing on an mbarrier (UBLKCP, no tensormap).
__device__ __forceinline__ void bulkcp(float* dst, const float* src, int bytes,
                                       unsigned mbar) {
    asm volatile("cp.async.bulk.shared::cta.global.mbarrier::complete_tx::bytes "
                 "[%0], [%1], %2, [%3];"
                 :: "r"(s2u(dst)), "l"(src), "r"(bytes), "r"(mbar) : "memory");
}
__device__ __forceinline__ void mbar_init(unsigned mbar, unsigned count) {
    asm volatile("mbarrier.init.shared.b64 [%0], %1;" :: "r"(mbar), "r"(count)
                 : "memory");
}
__device__ __forceinline__ void mbar_arrive_tx(unsigned mbar, unsigned bytes) {
    asm volatile("mbarrier.arrive.expect_tx.shared.b64 _, [%0], %1;"
                 :: "r"(mbar), "r"(bytes) : "memory");
}
__device__ __forceinline__ void mbar_wait(unsigned mbar, unsigned parity) {
    asm volatile(
        "{\n\t"
        ".reg .pred P;\n\t"
        "W%=:\n\t"
        "mbarrier.try_wait.parity.acquire.cta.shared::cta.b64 P, [%0], %1, 0x989680;\n\t"
        "@P bra D%=;\n\t"
        "bra W%=;\n\t"
        "D%=:\n\t"
        "}"
        :: "r"(mbar), "r"(parity) : "memory");
}

// ---------------------------------------------------------------------------
// Prefetch one tile's u, kappa, f into smem.
// Interior rows go via bulk copies (complete on mbar); clipped rows/tiles and
// the non-16B-aligned `pre` input fall back to per-16B cp.async (group-based).
// tid 0 always arrives with expect_tx (0 bytes when inactive) to flip phase.
// ---------------------------------------------------------------------------
template<bool VIN>
__device__ __forceinline__
void prefetch_tile(int t, float* UL, float* KS, float* FS,
                   const float* __restrict__ uin,
                   const float* __restrict__ kappa,
                   const float* __restrict__ f, int tid, unsigned mbar)
{
    const bool active = (t < NTILES);
    int b = 0, ti = 0, tj = 0;
    if (active) {
        b = t / (NTR * NTC);
        int r2 = t - b * (NTR * NTC);
        ti = r2 / NTC; tj = r2 - ti * NTC;
    }
    const int gi0 = ti * OUTR - T;
    const int gj0 = tj * OUTC - T;
    const size_t bK = (size_t)b * GV * GV;

    // bulk eligibility (full 72/68-wide row inside the padded row allocation;
    // scratch cols NV..1023 are permanently zero => correct OOB semantics)
    const bool bu = VIN && active && (gj0 - 4 >= 0) && (gj0 + 68 <= GV);
    const bool bk = active && (gj0 >= 0) && (gj0 + 68 <= GV);

    // in-bounds row ranges
    int u_lo = 1 - gi0;  if (u_lo < 0)  u_lo = 0;      // i = gi0-1+li >= 0
    int u_hi = NV + 1 - gi0; if (u_hi > UH) u_hi = UH; // i < NV
    int k_lo = -gi0;     if (k_lo < 0)  k_lo = 0;      // fr = gi0+r >= 0
    int k_hi = GV - gi0; if (k_hi > UH) k_hi = UH;     // fr < GV
    const int nu = bu ? (u_hi - u_lo) : 0;
    const int nk = bk ? (k_hi - k_lo) : 0;

    if (tid == 0) {
        mbar_arrive_tx(mbar, (unsigned)(nu * (UW * 4) + nk * 2 * (KW * 4)));
    }
    if (!active) return;

    // ---- bulk issues (one row per issuing thread) ----
    if (bu && tid >= 256 && tid < 256 + UH) {
        int li = tid - 256;
        if (li >= u_lo && li < u_hi) {
            const float* src = uin + (size_t)b * NV * SP
                             + (size_t)(gi0 - 1 + li) * SP + (gj0 - 4);
            bulkcp(UL + li * UW, src, UW * 4, mbar);
        }
    }
    if (bk && tid >= 320 && tid < 320 + UH) {
        int r = tid - 320;
        if (r >= k_lo && r < k_hi) {
            const size_t off = bK + (size_t)(gi0 + r) * GV + gj0;
            bulkcp(KS + r * KW, kappa + off, KW * 4, mbar);
            bulkcp(FS + r * KW, f     + off, KW * 4, mbar);
        }
    }

    // ---- fallback / zero-fill rows via per-16B cp.async ----
    // kappa + f
    for (int idx = tid; idx < UH * 17; idx += 512) {
        int r = idx / 17, q = idx - r * 17;
        if (bk && r >= k_lo && r < k_hi) continue;   // bulk covered
        int c  = 4 * q;
        int fr = gi0 + r, fc = gj0 + c;
        bool inb = (fr >= 0 && fr < GV && fc >= 0 && fc < GV);
        size_t off = bK + (size_t)(inb ? fr : 0) * GV + (inb ? fc : 0);
        cp16(KS + r * KW + c, kappa + off, inb);
        cp16(FS + r * KW + c, f     + off, inb);
    }
    // u
    if (VIN) {
        const size_t bU = (size_t)b * NV * SP;
        for (int idx = tid; idx < UH * 18; idx += 512) {
            int li = idx / 18, q = idx - li * 18;
            if (bu && li >= u_lo && li < u_hi) continue;   // bulk covered
            int lj = 4 * q;
            int i = gi0 - 1 + li, j = gj0 - 4 + lj;
            bool inb = (i >= 0 && i < NV && j >= 0 && j < NV);
            cp16(UL + li * UW + lj,
                 uin + bU + (size_t)(inb ? i : 0) * SP + (inb ? j : 0), inb);
        }
    } else {
        const size_t bU = (size_t)b * NV * NV;
        for (int idx = tid; idx < UH * 18; idx += 512) {
            int li = idx / 18, q = idx - li * 18;
            int lj = 4 * q;
            int i = gi0 - 1 + li, j = gj0 - 4 + lj;
            #pragma unroll
            for (int m = 0; m < 4; ++m) {
                int jj = j + m;
                bool inb = (i >= 0 && i < NV && jj >= 0 && jj < NV);
                cp4(UL + li * UW + lj + m,
                    uin + bU + (size_t)(inb ? i : 0) * NV + (inb ? jj : 0), inb);
            }
        }
    }
}

// ---------------------------------------------------------------------------
// Persistent fused kernel: grid-stride over tiles, double-buffered prefetch
// (bulk + cp.async hybrid). smem maps as before.
// ---------------------------------------------------------------------------
template<bool VIN, bool VOUT>
__global__ __launch_bounds__(512, 2)
void fused_kernel(const float* __restrict__ uin,
                  float*       __restrict__ uout,
                  const float* __restrict__ kappa,
                  const float* __restrict__ f)
{
    __shared__ __align__(128) float SM[3 * USZ + 2 * KSZ];   // 47872 bytes
    __shared__ __align__(8) unsigned long long mbar_s;
    float* UL0 = SM;
    float* UL1 = SM + USZ;
    float* USC = SM + 2 * USZ;
    float* KS  = SM + 3 * USZ;
    float* FS  = KS + KSZ;

    const int tid = threadIdx.x;
    const int tx = tid & 15;            // 0..15
    const int ty = tid >> 4;            // 0..31
    const int nb = gridDim.x;
    const int iters = (NTILES + nb - 1) / nb;
    const unsigned mbar = s2u(&mbar_s);

    if (tid == 0) mbar_init(mbar, 1);
    __syncthreads();

    // prologue: prefetch first tile
    prefetch_tile<VIN>(blockIdx.x, UL0, KS, FS, uin, kappa, f, tid, mbar);
    CP_COMMIT();

    const int li  = 1 + ty;             // owned row
    const int lj0 = 4 + 4 * tx;         // owned cols lj0..lj0+3

    for (int k = 0; k < iters; ++k) {
        int t = blockIdx.x + k * nb;
        bool active = (t < NTILES);
        float* Ua = (k & 1) ? UL1 : UL0;
        float* Ub = (k & 1) ? UL0 : UL1;

        CP_WAIT0();
        mbar_wait(mbar, (unsigned)(k & 1));
        __syncthreads();                 // tile-k data visible block-wide

        // ---- coefficients (registers) from KS/FS ----
        int b = 0, ti = 0, tj = 0, gi0 = 0, gj0 = 0;
        float cN[4], cS[4], cW[4], cE[4], fp[4];
        if (active) {
            b  = t / (NTR * NTC);
            int r2 = t - b * (NTR * NTC);
            ti = r2 / NTC; tj = r2 - ti * NTC;
            gi0 = ti * OUTR - T; gj0 = tj * OUTC - T;
            const int i = gi0 - 1 + li;
            #pragma unroll
            for (int cc = 0; cc < 4; ++cc) {
                int c = lj0 + cc - 3;
                int j = gj0 + c - 1;
                bool valid = (i >= 0 && i < NV && j >= 0 && j < NV);
                float kc = KS[li * KW + c];
                float kn = KS[(li - 1) * KW + c];
                float ks = KS[(li + 1) * KW + c];
                float kw = KS[li * KW + c - 1];
                float ke = KS[li * KW + c + 1];
                float aN = kc + kn, aS = kc + ks, aW = kc + kw, aE = kc + ke;
                float inv = __frcp_rn((aN + aS) + (aW + aE));
                cN[cc] = valid ? aN * inv : 0.0f;
                cS[cc] = valid ? aS * inv : 0.0f;
                cW[cc] = valid ? aW * inv : 0.0f;
                cE[cc] = valid ? aE * inv : 0.0f;
                fp[cc] = valid ? FS[li * KW + c] * (HH2 * inv) : 0.0f;
            }
        } else {
            #pragma unroll
            for (int cc = 0; cc < 4; ++cc) {
                cN[cc] = cS[cc] = cW[cc] = cE[cc] = fp[cc] = 0.0f;
            }
        }

        __syncthreads();                 // KS/FS reads done before overwrite

        // ---- prefetch next tile (overlaps the sweeps below) ----
        prefetch_tile<VIN>(blockIdx.x + (k + 1) * nb, Ub, KS, FS,
                           uin, kappa, f, tid, mbar);
        CP_COMMIT();

        // ---- T sweeps, ping-pong Ua <-> USC, one barrier per sweep ----
        float* src = Ua;
        float* dst = USC;
        #pragma unroll
        for (int s = 0; s < T; ++s) {
            float4 up = *(const float4*)(src + (li - 1) * UW + lj0);
            float4 ce = *(const float4*)(src + li * UW + lj0);
            float4 dn = *(const float4*)(src + (li + 1) * UW + lj0);
            float  cl = src[li * UW + lj0 - 1];
            float  cr = src[li * UW + lj0 + 4];

            float4 r;
            r.x = fmaf(cN[0], up.x, fp[0]);
            r.x = fmaf(cS[0], dn.x, r.x);
            r.x = fmaf(cW[0], cl,   r.x);
            r.x = fmaf(cE[0], ce.y, r.x);

            r.y = fmaf(cN[1], up.y, fp[1]);
            r.y = fmaf(cS[1], dn.y, r.y);
            r.y = fmaf(cW[1], ce.x, r.y);
            r.y = fmaf(cE[1], ce.z, r.y);

            r.z = fmaf(cN[2], up.z, fp[2]);
            r.z = fmaf(cS[2], dn.z, r.z);
            r.z = fmaf(cW[2], ce.y, r.z);
            r.z = fmaf(cE[2], ce.w, r.z);

            r.w = fmaf(cN[3], up.w, fp[3]);
            r.w = fmaf(cS[3], dn.w, r.w);
            r.w = fmaf(cW[3], ce.z, r.w);
            r.w = fmaf(cE[3], cr,   r.w);

            *(float4*)(dst + li * UW + lj0) = r;
            __syncthreads();
            float* tmp = src; src = dst; dst = tmp;
        }
        // T even -> final result in Ua

        // ---- emit valid 24x56 region (li 5..28, lj 8..63) ----
        if (active) {
            const size_t bO = VOUT ? (size_t)b * NV * SP : (size_t)b * NV * NV;
            for (int idx = tid; idx < OUTR * 14; idx += 512) {
                int row = idx / 14, q = idx - row * 14;
                int lli = 1 + T + row;
                int llj = 4 + T + 4 * q;
                int i = ti * OUTR + row;
                int j = tj * OUTC + 4 * q;
                if (i >= NV) continue;
                float4 v = *(const float4*)(Ua + lli * UW + llj);
                if (VOUT && j + 3 < NV) {
                    *(float4*)(uout + bO + (size_t)i * SP + j) = v;
                } else {
                    float tv[4] = {v.x, v.y, v.z, v.w};
                    #pragma unroll
                    for (int m = 0; m < 4; ++m)
                        if (j + m < NV)
                            uout[bO + (size_t)i * (VOUT ? SP : NV) + j + m] = tv[m];
                }
            }
        }
        // next iteration's top barrier orders epilogue reads vs. buffer reuse
    }
}

// ---------------------------------------------------------------------------
extern "C" void kernel_launch(void* const* d_in, const int* in_sizes, int n_in,
                              void* d_out, int out_size) {
    const float* pre   = (const float*)d_in[0];   // (8,1,1022,1022)
    const float* f     = (const float*)d_in[1];   // (8,1,1024,1024)
    const float* kappa = (const float*)d_in[2];   // (8,1,1024,1024)
    float* out = (float*)d_out;                   // (8,1,1022,1022)

    float *A, *B;
    cudaGetSymbolAddress((void**)&A, g_bufA);
    cudaGetSymbolAddress((void**)&B, g_bufB);

    cudaFuncSetAttribute(fused_kernel<false, true>,
        cudaFuncAttributePreferredSharedMemoryCarveout, 100);
    cudaFuncSetAttribute(fused_kernel<true, true>,
        cudaFuncAttributePreferredSharedMemoryCarveout, 100);
    cudaFuncSetAttribute(fused_kernel<true, false>,
        cudaFuncAttributePreferredSharedMemoryCarveout, 100);

    int dev = 0, nsm = 148;
    cudaGetDevice(&dev);
    cudaDeviceGetAttribute(&nsm, cudaDevAttrMultiProcessorCount, dev);
    int nblocks = 2 * nsm;

    dim3 blk(512, 1, 1);
    dim3 grd(nblocks, 1, 1);

    // 16 sweeps = 4 fused kernels of T=4
    fused_kernel<false, true><<<grd, blk>>>(pre, A, kappa, f);
    fused_kernel<true,  true><<<grd, blk>>>(A,   B, kappa, f);
    fused_kernel<true,  true><<<grd, blk>>>(B,   A, kappa, f);
    fused_kernel<true, false><<<grd, blk>>>(A, out, kappa, f);
}

// round 17
// speedup vs baseline: 1.3149x; 1.3149x over previous
#include <cuda_runtime.h>

#define NV 1022            // interior size
#define GV 1024            // full grid
#define SP 1024            // padded scratch row stride

#define T    4             // fused sweeps per kernel
#define OUTR 24            // valid output rows per tile
#define OUTC 56            // valid output cols per tile
#define NTR  43            // ceil(1022/24)
#define NTC  19            // ceil(1022/56)
#define NTILES (8 * NTR * NTC)

#define UH 34              // smem u rows
#define UW 72              // smem u row stride
#define KW 68              // smem kappa/f row stride
#define USZ (UH * UW)      // 2448
#define KSZ (UH * KW)      // 2312
#define SMEM_FLOATS (3 * USZ + 4 * KSZ)          // 16592
#define SMEM_BYTES  (SMEM_FLOATS * 4)            // 66368

#define HH2 (2.0f / (1023.0f * 1023.0f))   // 2*H^2

__device__ __align__(256) float g_bufA[8 * NV * SP];
__device__ __align__(256) float g_bufB[8 * NV * SP];

// ---------------------------------------------------------------------------
__device__ __forceinline__ unsigned s2u(const void* p) {
    unsigned r;
    asm("{ .reg .u64 t; cvta.to.shared.u64 t, %1; cvt.u32.u64 %0, t; }"
        : "=r"(r) : "l"(p));
    return r;
}
// 16B async copy, L1-bypass (.cg), zero-fill when out of bounds
__device__ __forceinline__ void cp16(float* dst, const float* src, bool inb) {
    int sz = inb ? 16 : 0;
    asm volatile("cp.async.cg.shared.global [%0], [%1], 16, %2;"
                 :: "r"(s2u(dst)), "l"(src), "r"(sz) : "memory");
}
__device__ __forceinline__ void cp4(float* dst, const float* src, bool inb) {
    int sz = inb ? 4 : 0;
    asm volatile("cp.async.ca.shared.global [%0], [%1], 4, %2;"
                 :: "r"(s2u(dst)), "l"(src), "r"(sz) : "memory");
}
#define CP_COMMIT() asm volatile("cp.async.commit_group;" ::: "memory")
#define CP_WAIT0()  asm volatile("cp.async.wait_group 0;"  ::: "memory")

// ---------------------------------------------------------------------------
// one kappa+f 16B chunk (idx in [0, UH*17))
__device__ __forceinline__
void kf_chunk(int idx, int gi0, int gj0, size_t bK, float* KS, float* FS,
              const float* __restrict__ kappa, const float* __restrict__ f)
{
    int r = idx / 17, q = idx - r * 17;
    int c  = 4 * q;
    int fr = gi0 + r, fc = gj0 + c;
    bool inb = (fr >= 0 && fr < GV && fc >= 0 && fc < GV);  // fc%4==0 -> fc+3<GV
    size_t off = bK + (size_t)(inb ? fr : 0) * GV + (inb ? fc : 0);
    cp16(KS + r * KW + c, kappa + off, inb);
    cp16(FS + r * KW + c, f     + off, inb);
}

// one u 16B chunk, padded-scratch input (idx in [0, UH*18))
__device__ __forceinline__
void u_chunk_v(int idx, int gi0, int gj0, size_t bU, float* UL,
               const float* __restrict__ uin)
{
    int li = idx / 18, q = idx - li * 18;
    int lj = 4 * q;
    int i = gi0 - 1 + li, j = gj0 - 4 + lj;
    // scratch rows have zero cols NV..SP-1, so j<NV suffices (j%4==0)
    bool inb = (i >= 0 && i < NV && j >= 0 && j < NV);
    cp16(UL + li * UW + lj,
         uin + bU + (size_t)(inb ? i : 0) * SP + (inb ? j : 0), inb);
}

// one u chunk, tight-stride input (`pre`), 4 scalar copies
__device__ __forceinline__
void u_chunk_s(int idx, int gi0, int gj0, size_t bU, float* UL,
               const float* __restrict__ uin)
{
    int li = idx / 18, q = idx - li * 18;
    int lj = 4 * q;
    int i = gi0 - 1 + li, j = gj0 - 4 + lj;
    #pragma unroll
    for (int m = 0; m < 4; ++m) {
        int jj = j + m;
        bool inb = (i >= 0 && i < NV && jj >= 0 && jj < NV);
        cp4(UL + li * UW + lj + m,
            uin + bU + (size_t)(inb ? i : 0) * NV + (inb ? jj : 0), inb);
    }
}

template<bool VIN>
__device__ __forceinline__
void prefetch_tile(int t, float* UL, float* KS, float* FS,
                   const float* __restrict__ uin,
                   const float* __restrict__ kappa,
                   const float* __restrict__ f, int tid)
{
    if (t >= NTILES) return;
    int b  = t / (NTR * NTC);
    int r2 = t - b * (NTR * NTC);
    int ti = r2 / NTC, tj = r2 - ti * NTC;
    int gi0 = ti * OUTR - T;
    int gj0 = tj * OUTC - T;
    const size_t bK = (size_t)b * GV * GV;

    // kappa + f: UH*17 = 578 chunks over 512 threads (2 trips)
    kf_chunk(tid, gi0, gj0, bK, KS, FS, kappa, f);
    if (tid < UH * 17 - 512)
        kf_chunk(tid + 512, gi0, gj0, bK, KS, FS, kappa, f);

    // u: UH*18 = 612 chunks over 512 threads (2 trips)
    if (VIN) {
        const size_t bU = (size_t)b * NV * SP;
        u_chunk_v(tid, gi0, gj0, bU, UL, uin);
        if (tid < UH * 18 - 512)
            u_chunk_v(tid + 512, gi0, gj0, bU, UL, uin);
    } else {
        const size_t bU = (size_t)b * NV * NV;
        u_chunk_s(tid, gi0, gj0, bU, UL, uin);
        if (tid < UH * 18 - 512)
            u_chunk_s(tid + 512, gi0, gj0, bU, UL, uin);
    }
}

// ---------------------------------------------------------------------------
// Persistent fused kernel. Per tile:
//   wait(prefetch k) -> bar -> issue prefetch k+1 (double-buffered u AND k/f)
//   -> coeffs (regs) -> sweeps 0..2 (STS + bar) -> sweep 3 (direct STG, no bar)
// 4 barriers per tile total.
// ---------------------------------------------------------------------------
template<bool VIN, bool VOUT>
__global__ __launch_bounds__(512, 2)
void fused_kernel(const float* __restrict__ uin,
                  float*       __restrict__ uout,
                  const float* __restrict__ kappa,
                  const float* __restrict__ f)
{
    extern __shared__ __align__(128) float SM[];
    float* UL0 = SM;
    float* UL1 = SM + USZ;
    float* USC = SM + 2 * USZ;
    float* KS0 = SM + 3 * USZ;
    float* FS0 = KS0 + KSZ;
    float* KS1 = FS0 + KSZ;
    float* FS1 = KS1 + KSZ;

    const int tid = threadIdx.x;
    const int tx = tid & 15;            // 0..15
    const int ty = tid >> 4;            // 0..31
    const int nb = gridDim.x;
    const int iters = (NTILES + nb - 1) / nb;

    // prologue: prefetch first tile into buffer set 0
    prefetch_tile<VIN>(blockIdx.x, UL0, KS0, FS0, uin, kappa, f, tid);
    CP_COMMIT();

    const int li  = 1 + ty;             // owned row
    const int lj0 = 4 + 4 * tx;         // owned cols lj0..lj0+3

    for (int k = 0; k < iters; ++k) {
        int t = blockIdx.x + k * nb;
        bool active = (t < NTILES);
        float* Ua  = (k & 1) ? UL1 : UL0;
        float* Ub  = (k & 1) ? UL0 : UL1;
        float* KSa = (k & 1) ? KS1 : KS0;
        float* FSa = (k & 1) ? FS1 : FS0;
        float* KSb = (k & 1) ? KS0 : KS1;
        float* FSb = (k & 1) ? FS0 : FS1;

        CP_WAIT0();
        __syncthreads();                 // tile-k data visible block-wide

        // ---- prefetch tile k+1 immediately (other buffer set) ----
        prefetch_tile<VIN>(blockIdx.x + (k + 1) * nb, Ub, KSb, FSb,
                           uin, kappa, f, tid);
        CP_COMMIT();

        // ---- coefficients (registers) from KSa/FSa ----
        int b = 0, ti = 0, tj = 0;
        float cN[4], cS[4], cW[4], cE[4], fp[4];
        if (active) {
            b  = t / (NTR * NTC);
            int r2 = t - b * (NTR * NTC);
            ti = r2 / NTC; tj = r2 - ti * NTC;
            const int gi0 = ti * OUTR - T;
            const int gj0 = tj * OUTC - T;
            const int i = gi0 - 1 + li;
            const bool rv = (i >= 0 && i < NV);
            const int base = li * KW + lj0;
            float kcn[6], kup[4], kdn[4], fl[4];
            #pragma unroll
            for (int m = 0; m < 6; ++m) kcn[m] = KSa[base - 4 + m];
            #pragma unroll
            for (int m = 0; m < 4; ++m) {
                kup[m] = KSa[base - KW - 3 + m];
                kdn[m] = KSa[base + KW - 3 + m];
                fl[m]  = FSa[base - 3 + m];
            }
            #pragma unroll
            for (int cc = 0; cc < 4; ++cc) {
                int j = gj0 + lj0 - 4 + cc;          // interior col
                bool valid = rv && (j >= 0 && j < NV);
                float kc = kcn[cc + 1];
                float aN = kc + kup[cc];
                float aS = kc + kdn[cc];
                float aW = kc + kcn[cc];
                float aE = kc + kcn[cc + 2];
                float inv = __frcp_rn((aN + aS) + (aW + aE));
                cN[cc] = valid ? aN * inv : 0.0f;
                cS[cc] = valid ? aS * inv : 0.0f;
                cW[cc] = valid ? aW * inv : 0.0f;
                cE[cc] = valid ? aE * inv : 0.0f;
                fp[cc] = valid ? fl[cc] * (HH2 * inv) : 0.0f;
            }
        } else {
            #pragma unroll
            for (int cc = 0; cc < 4; ++cc)
                cN[cc] = cS[cc] = cW[cc] = cE[cc] = fp[cc] = 0.0f;
        }

        // ---- sweeps 0..2: smem ping-pong Ua -> USC -> Ua -> USC ----
        float* src = Ua;
        float* dst = USC;
        #pragma unroll
        for (int s = 0; s < 3; ++s) {
            float4 up = *(const float4*)(src + (li - 1) * UW + lj0);
            float4 ce = *(const float4*)(src + li * UW + lj0);
            float4 dn = *(const float4*)(src + (li + 1) * UW + lj0);
            float  cl = src[li * UW + lj0 - 1];
            float  cr = src[li * UW + lj0 + 4];

            float4 r;
            r.x = fmaf(cN[0], up.x, fp[0]);
            r.x = fmaf(cS[0], dn.x, r.x);
            r.x = fmaf(cW[0], cl,   r.x);
            r.x = fmaf(cE[0], ce.y, r.x);

            r.y = fmaf(cN[1], up.y, fp[1]);
            r.y = fmaf(cS[1], dn.y, r.y);
            r.y = fmaf(cW[1], ce.x, r.y);
            r.y = fmaf(cE[1], ce.z, r.y);

            r.z = fmaf(cN[2], up.z, fp[2]);
            r.z = fmaf(cS[2], dn.z, r.z);
            r.z = fmaf(cW[2], ce.y, r.z);
            r.z = fmaf(cE[2], ce.w, r.z);

            r.w = fmaf(cN[3], up.w, fp[3]);
            r.w = fmaf(cS[3], dn.w, r.w);
            r.w = fmaf(cW[3], ce.z, r.w);
            r.w = fmaf(cE[3], cr,   r.w);

            *(float4*)(dst + li * UW + lj0) = r;
            __syncthreads();
            float* tmp = src; src = dst; dst = tmp;
        }
        // after 3 sweeps: latest data in USC (src == USC)

        // ---- sweep 3: compute in regs, store owned valid points to GMEM ----
        {
            float4 up = *(const float4*)(src + (li - 1) * UW + lj0);
            float4 ce = *(const float4*)(src + li * UW + lj0);
            float4 dn = *(const float4*)(src + (li + 1) * UW + lj0);
            float  cl = src[li * UW + lj0 - 1];
            float  cr = src[li * UW + lj0 + 4];

            float4 r;
            r.x = fmaf(cN[0], up.x, fp[0]);
            r.x = fmaf(cS[0], dn.x, r.x);
            r.x = fmaf(cW[0], cl,   r.x);
            r.x = fmaf(cE[0], ce.y, r.x);

            r.y = fmaf(cN[1], up.y, fp[1]);
            r.y = fmaf(cS[1], dn.y, r.y);
            r.y = fmaf(cW[1], ce.x, r.y);
            r.y = fmaf(cE[1], ce.z, r.y);

            r.z = fmaf(cN[2], up.z, fp[2]);
            r.z = fmaf(cS[2], dn.z, r.z);
            r.z = fmaf(cW[2], ce.y, r.z);
            r.z = fmaf(cE[2], ce.w, r.z);

            r.w = fmaf(cN[3], up.w, fp[3]);
            r.w = fmaf(cS[3], dn.w, r.w);
            r.w = fmaf(cW[3], ce.z, r.w);
            r.w = fmaf(cE[3], cr,   r.w);

            // owned point is in the valid cone iff ty in [4,27], tx in [1,14]
            if (active && ty >= 4 && ty <= 27 && tx >= 1 && tx <= 14) {
                int i = ti * OUTR + (ty - 4);
                int j = tj * OUTC + 4 * (tx - 1);
                if (i < NV) {
                    const size_t bO = VOUT ? (size_t)b * NV * SP
                                           : (size_t)b * NV * NV;
                    if (VOUT && j + 3 < NV) {
                        *(float4*)(uout + bO + (size_t)i * SP + j) = r;
                    } else {
                        float tv[4] = {r.x, r.y, r.z, r.w};
                        #pragma unroll
                        for (int m = 0; m < 4; ++m)
                            if (j + m < NV)
                                uout[bO + (size_t)i * (VOUT ? SP : NV) + j + m] = tv[m];
                    }
                }
            }
        }
        // next iteration's top barrier orders sweep-3 smem reads vs. reuse
    }
}

// ---------------------------------------------------------------------------
extern "C" void kernel_launch(void* const* d_in, const int* in_sizes, int n_in,
                              void* d_out, int out_size) {
    const float* pre   = (const float*)d_in[0];   // (8,1,1022,1022)
    const float* f     = (const float*)d_in[1];   // (8,1,1024,1024)
    const float* kappa = (const float*)d_in[2];   // (8,1,1024,1024)
    float* out = (float*)d_out;                   // (8,1,1022,1022)

    float *A, *B;
    cudaGetSymbolAddress((void**)&A, g_bufA);
    cudaGetSymbolAddress((void**)&B, g_bufB);

    cudaFuncSetAttribute(fused_kernel<false, true>,
        cudaFuncAttributeMaxDynamicSharedMemorySize, SMEM_BYTES);
    cudaFuncSetAttribute(fused_kernel<true, true>,
        cudaFuncAttributeMaxDynamicSharedMemorySize, SMEM_BYTES);
    cudaFuncSetAttribute(fused_kernel<true, false>,
        cudaFuncAttributeMaxDynamicSharedMemorySize, SMEM_BYTES);

    int nsm = 0;
    if (cudaDeviceGetAttribute(&nsm, cudaDevAttrMultiProcessorCount, 0)
            != cudaSuccess || nsm <= 0) {
        nsm = 148;
    }
    int nblocks = 2 * nsm;

    dim3 blk(512, 1, 1);
    dim3 grd(nblocks, 1, 1);

    // 16 sweeps = 4 fused kernels of T=4
    fused_kernel<false, true><<<grd, blk, SMEM_BYTES>>>(pre, A, kappa, f);
    fused_kernel<true,  true><<<grd, blk, SMEM_BYTES>>>(A,   B, kappa, f);
    fused_kernel<true,  true><<<grd, blk, SMEM_BYTES>>>(B,   A, kappa, f);
    fused_kernel<true, false><<<grd, blk, SMEM_BYTES>>>(A, out, kappa, f);
}